// round 1
// baseline (speedup 1.0000x reference)
#include <cuda_runtime.h>
#include <cstdint>

// Problem constants
#define TT      512
#define BB      256
#define HH      128
#define EE      256
#define VV      82
#define HE      384     // HIDDEN + EMBED
#define G3H     384     // 3 gates * H

// Scratch: precomputed x-projection table: xtable[v][g*H+u], g: 0=f, 1=o, 2=c_tilde
__device__ float g_xtable[VV * G3H];

// ---------------------------------------------------------------------------
// packed f32x2 helpers
// ---------------------------------------------------------------------------
__device__ __forceinline__ unsigned long long ffma2(unsigned long long a,
                                                    unsigned long long b,
                                                    unsigned long long c) {
    unsigned long long d;
    asm("fma.rn.f32x2 %0, %1, %2, %3;" : "=l"(d) : "l"(a), "l"(b), "l"(c));
    return d;
}

__device__ __forceinline__ float2 unpack2(unsigned long long v) {
    float2 r;
    asm("mov.b64 {%0, %1}, %2;" : "=f"(r.x), "=f"(r.y) : "l"(v));
    return r;
}

__device__ __forceinline__ float sigmoid_f(float x) {
    return __fdividef(1.0f, 1.0f + __expf(-x));
}
__device__ __forceinline__ float tanh_f(float x) {
    // tanh(x) = 1 - 2/(exp(2x)+1); saturates correctly for large |x|
    return 1.0f - __fdividef(2.0f, __expf(2.0f * x) + 1.0f);
}

// ---------------------------------------------------------------------------
// Kernel 1: xtable[v][g*128+u] = sum_k emb[v][k] * W_g[u][128+k]
// Gate order g: 0 = W_f, 1 = W_o, 2 = W_c
// ---------------------------------------------------------------------------
__global__ void xtable_kernel(const float* __restrict__ emb,
                              const float* __restrict__ Wf,
                              const float* __restrict__ Wc,
                              const float* __restrict__ Wo) {
    int v = blockIdx.x;          // 0..81
    int j = threadIdx.x;         // 0..383
    int g = j >> 7;
    int u = j & 127;
    const float* W = (g == 0) ? Wf : ((g == 1) ? Wo : Wc);
    const float* wrow = W + u * HE + HH;     // x-part of row u
    const float* e = emb + v * EE;
    float s = 0.0f;
#pragma unroll 8
    for (int k = 0; k < EE; k++) s += e[k] * wrow[k];
    g_xtable[v * G3H + j] = s;
}

// ---------------------------------------------------------------------------
// Kernel 2: recurrence. 128 blocks x 384 threads; each block owns 2 batch rows.
// Thread j owns W_h row (gate g = j>>7, unit u = j&127), kept in 64 packed regs.
// ---------------------------------------------------------------------------
__global__ void __launch_bounds__(384, 1)
lstm_kernel(const int*   __restrict__ tokens,   // [B, T]
            const float* __restrict__ Wf,
            const float* __restrict__ Wc,
            const float* __restrict__ Wo,
            const float* __restrict__ clfW,     // [V, H]
            const float* __restrict__ clfb,     // [V]
            float* __restrict__ out) {
    __shared__ __align__(16) float sh_h[2][HH];
    __shared__ __align__(16) float sh_c[2][HH];
    __shared__ float sh_g[2][G3H];
    __shared__ int   sh_tok[2][TT];

    const int j  = threadIdx.x;          // 0..383
    const int g  = j >> 7;
    const int u  = j & 127;
    const int b0 = blockIdx.x * 2;       // global batch of lane 0

    // ---- load this thread's W_h row into registers as 64 packed f32x2 ----
    const float* Wsel = (g == 0) ? Wf : ((g == 1) ? Wo : Wc);
    const ulonglong2* wp = reinterpret_cast<const ulonglong2*>(Wsel + (size_t)u * HE);
    unsigned long long w[64];
#pragma unroll
    for (int i = 0; i < 32; i++) {
        ulonglong2 t = wp[i];     // 16B: floats [4i..4i+3] of the h-part
        w[2 * i]     = t.x;
        w[2 * i + 1] = t.y;
    }

    // ---- init h, c = 0; stage tokens into smem ----
    for (int i = j; i < 2 * HH; i += 384) {
        (&sh_h[0][0])[i] = 0.0f;
        (&sh_c[0][0])[i] = 0.0f;
    }
    for (int i = j; i < 2 * TT; i += 384) {
        (&sh_tok[0][0])[i] = tokens[(size_t)(b0 + i / TT) * TT + (i % TT)];
    }
    __syncthreads();

    const size_t gateSz = (size_t)TT * BB * HH;
    float* f_out = out + (size_t)BB * VV;
    float* o_out = f_out + gateSz;
    float* c_out = o_out + gateSz;

    for (int t = 0; t < TT; t++) {
        // issue x-part loads early (L2-resident table) so LDG overlaps FMA loop
        const int tok0 = sh_tok[0][t];
        const int tok1 = sh_tok[1][t];
        const float x0 = g_xtable[tok0 * G3H + j];
        const float x1 = g_xtable[tok1 * G3H + j];

        const ulonglong2* h0p = reinterpret_cast<const ulonglong2*>(sh_h[0]);
        const ulonglong2* h1p = reinterpret_cast<const ulonglong2*>(sh_h[1]);

        unsigned long long a0 = 0ull, a1 = 0ull, a2 = 0ull, a3 = 0ull;
#pragma unroll
        for (int i = 0; i < 32; i++) {
            ulonglong2 hv0 = h0p[i];        // broadcast LDS.128
            a0 = ffma2(hv0.x, w[2 * i],     a0);
            a1 = ffma2(hv0.y, w[2 * i + 1], a1);
            ulonglong2 hv1 = h1p[i];
            a2 = ffma2(hv1.x, w[2 * i],     a2);
            a3 = ffma2(hv1.y, w[2 * i + 1], a3);
        }
        float2 p0 = unpack2(a0), p1 = unpack2(a1);
        float2 p2 = unpack2(a2), p3 = unpack2(a3);
        const float s0 = (p0.x + p0.y) + (p1.x + p1.y) + x0;
        const float s1 = (p2.x + p2.y) + (p3.x + p3.y) + x1;

        const float v0 = (g == 2) ? tanh_f(s0) : sigmoid_f(s0);
        const float v1 = (g == 2) ? tanh_f(s1) : sigmoid_f(s1);
        sh_g[0][j] = v0;
        sh_g[1][j] = v1;
        __syncthreads();

        if (j < 256) {
            const int b  = j >> 7;
            const int uu = j & 127;
            const float fv  = sh_g[b][uu];
            const float ov  = sh_g[b][HH + uu];
            const float ctv = sh_g[b][2 * HH + uu];
            const float cn  = fv * sh_c[b][uu] + (1.0f - fv) * ctv;
            const float hn  = ov * tanh_f(cn);
            sh_c[b][uu] = cn;
            sh_h[b][uu] = hn;
            const size_t base = ((size_t)t * BB + (b0 + b)) * HH + uu;
            f_out[base] = fv;
            o_out[base] = ov;
            c_out[base] = ctv;
        }
        __syncthreads();
    }

    // ---- logits: h_T @ clf_W.T + clf_b  (2 batches x 82 vocab) ----
    if (j < 2 * VV) {
        const int b = j / VV;
        const int v = j % VV;
        float s = clfb[v];
        const float* wc = clfW + (size_t)v * HH;
#pragma unroll 8
        for (int k = 0; k < HH; k++) s += sh_h[b][k] * wc[k];
        out[(size_t)(b0 + b) * VV + v] = s;
    }
}

// ---------------------------------------------------------------------------
// kernel_launch
// Inputs (metadata order): batch_reviews(int32 [256,512]), emb(f32 [82,256]),
//   W_f(f32 [128,384]), W_c(f32 [128,384]), W_o(f32 [128,384]),
//   clf_W(f32 [82,128]), clf_b(f32 [82])
// Output (f32): logits [256*82] | f_all [512*256*128] | o_all | ct_all
// ---------------------------------------------------------------------------
extern "C" void kernel_launch(void* const* d_in, const int* in_sizes, int n_in,
                              void* d_out, int out_size) {
    const int*   tokens = (const int*)  d_in[0];
    const float* emb    = (const float*)d_in[1];
    const float* Wf     = (const float*)d_in[2];
    const float* Wc     = (const float*)d_in[3];
    const float* Wo     = (const float*)d_in[4];
    const float* clfW   = (const float*)d_in[5];
    const float* clfb   = (const float*)d_in[6];
    float* out = (float*)d_out;

    xtable_kernel<<<VV, G3H>>>(emb, Wf, Wc, Wo);
    lstm_kernel<<<BB / 2, G3H>>>(tokens, Wf, Wc, Wo, clfW, clfb, out);
}